// round 15
// baseline (speedup 1.0000x reference)
#include <cuda_runtime.h>
#include <cstdint>

#define BN   32
#define CIN  256
#define COUT 256
#define HIN  64
#define WIN  64
#define OH   32
#define OW   32

#define ROW_S  72                  // floats per row in x stage
#define CI_S   648                 // 9 rows * 72
#define SBUF   10368               // 16 ci planes per buffer
#define NBUF   3
#define SM_BYTES (NBUF * SBUF * 4) // 124416 B

#define NWA (9 * 32 * 16 * 128)    // weights: tap x ks x mt x lane x 4

// Weights in mma-fragment order: [tap][ks][mt][lane][q], tf32-RNA rounded
__device__ __align__(16) float g_wA[NWA];

__device__ __forceinline__ uint32_t smem_u32(const void* p) {
    uint32_t a;
    asm("{ .reg .u64 t; cvta.to.shared.u64 t, %1; cvt.u32.u64 %0, t; }" : "=r"(a) : "l"(p));
    return a;
}

__global__ void prep_w(const float* __restrict__ w) {
    int idx = blockIdx.x * 256 + threadIdx.x;
    if (idx >= NWA) return;
    int q  = idx & 3;
    int l  = (idx >> 2) & 31;
    int mt = (idx >> 7) & 15;
    int ks = (idx >> 11) & 31;
    int t  = idx >> 16;
    int m  = mt * 16 + (l >> 2) + (q & 1) * 8;
    int ci = ks * 8 + (l & 3) + ((q >> 1) & 1) * 4;
    float v = w[((size_t)m * CIN + ci) * 9 + t];
    float o;
    asm("cvt.rna.tf32.f32 %0, %1;" : "=f"(o) : "f"(v));
    g_wA[idx] = o;
}

// CTA: m256 (all couts) x n128 (4 output rows). 256 threads, 8 warps,
// warp tile m64n64. Triple-buffered x stage, one ci-group (16) per buffer.
__global__ __launch_bounds__(256, 1)
void conv_mma(const float* __restrict__ x, float* __restrict__ out) {
    extern __shared__ __align__(16) float xs[];
    const int tid  = threadIdx.x;
    const int lane = tid & 31;
    const int warp = tid >> 5;
    const int warpM = warp >> 1;     // 0..3 : 64-cout slab
    const int warpN = warp & 1;      // 0..1 : 2 output rows each
    const int gid = lane >> 2;
    const int tig = lane & 3;
    const int R  = blockIdx.x * 4;   // 4 output rows per CTA
    const int b  = blockIdx.y;

    const uint32_t xs_base = smem_u32(xs);

    // zero the iw=-1 pad word (float idx 3) per (ci,row) in all 3 buffers
    for (int i = tid; i < NBUF * 144; i += 256) {
        int bf = i / 144;
        int r144 = i % 144;
        int ci = r144 / 9, row = r144 % 9;
        uint32_t d = xs_base + (uint32_t)(bf * SBUF + ci * CI_S + row * ROW_S + 3) * 4;
        asm volatile("st.shared.f32 [%0], 0f00000000;" :: "r"(d));
    }
    __syncthreads();

    // ---- fill group g's x tile into buffer buf (16B cp.async, zfill top pad) ----
    auto fill = [&](int g, int buf) {
        const float* xg = x + ((size_t)b * CIN + g * 16) * (HIN * WIN);
        const uint32_t dstb = xs_base + (uint32_t)buf * (SBUF * 4);
#pragma unroll
        for (int k = 0; k < 9; k++) {
            int i = k * 256 + tid;
            int ci  = i / 144;
            int rem = i % 144;
            int row = rem >> 4, c4 = rem & 15;
            int ir  = 2 * R - 1 + row;
            uint32_t d = dstb + (uint32_t)(ci * CI_S + row * ROW_S + 4 + 4 * c4) * 4;
            const float* s = xg + (size_t)ci * (HIN * WIN) + ir * WIN + 4 * c4;
            int sz = (ir >= 0) ? 16 : 0;
            asm volatile("cp.async.ca.shared.global [%0], [%1], 16, %2;"
                         :: "r"(d), "l"(s), "r"(sz));
        }
        asm volatile("cp.async.commit_group;" ::: "memory");
    };

    float acc[4][8][4];
#pragma unroll
    for (int mt = 0; mt < 4; mt++)
#pragma unroll
        for (int nt = 0; nt < 8; nt++)
#pragma unroll
            for (int q = 0; q < 4; q++) acc[mt][nt][q] = 0.f;

    fill(0, 0);
    fill(1, 1);

    // thread-invariant part of B byte address (within buffer)
    const uint32_t tb0 = (uint32_t)(tig * CI_S + 4 * warpN * ROW_S + 3 + 2 * gid) * 4;
    const float4* Abase = (const float4*)g_wA + (size_t)(warpM * 4) * 32 + lane;

    // prefetch A for (g=0, step=0): t=0, ks=0
    uint4 A0, A1, A2, A3;
    {
        const float4* ap = Abase;
        float4 f0 = ap[0], f1 = ap[32], f2 = ap[64], f3 = ap[96];
        A0 = *(uint4*)&f0; A1 = *(uint4*)&f1; A2 = *(uint4*)&f2; A3 = *(uint4*)&f3;
    }

    int buf = 0;
    for (int g = 0; g < 16; g++) {
        asm volatile("cp.async.wait_group 1;" ::: "memory");
        __syncthreads();
        // overlap: start fill(g+2) into the buffer consumed at group g-1
        if (g < 14) {
            int nb = buf + 2;
            if (nb >= NBUF) nb -= NBUF;
            fill(g + 2, nb);
        }

        const uint32_t bufb = xs_base + (uint32_t)buf * (SBUF * 4);

#pragma unroll 2
        for (int step = 0; step < 18; step++) {
            const int t   = step >> 1;
            const int ksl = step & 1;
            const int kh  = t / 3;
            const int kw  = t % 3;

            // prefetch A for next step (wraps into next group's step 0)
            uint4 N0, N1, N2, N3;
            {
                int gn = g, sn = step + 1;
                if (sn == 18) { sn = 0; gn = (g < 15) ? g + 1 : 15; }
                int tn = sn >> 1;
                int kn = gn * 2 + (sn & 1);
                const float4* ap = Abase + (size_t)((tn * 32 + kn) * 16) * 32;
                float4 f0 = ap[0], f1 = ap[32], f2 = ap[64], f3 = ap[96];
                N0 = *(uint4*)&f0; N1 = *(uint4*)&f1; N2 = *(uint4*)&f2; N3 = *(uint4*)&f3;
            }

            const uint32_t abase = bufb + tb0 +
                (uint32_t)(kh * ROW_S + kw + ksl * 8 * CI_S) * 4;

            // B: batch all 16 loads, then all 16 cvts (explicit MLP)
            float v0[8], v1[8];
#pragma unroll
            for (int nt = 0; nt < 8; nt++) {
                const uint32_t ba = abase + (nt >> 2) * 576 + (nt & 3) * 64;
                asm volatile("ld.shared.f32 %0, [%1];" : "=f"(v0[nt]) : "r"(ba));
                asm volatile("ld.shared.f32 %0, [%1];" : "=f"(v1[nt])
                             : "r"(ba + 4 * CI_S * 4));
            }
            uint32_t b0[8], b1[8];
#pragma unroll
            for (int nt = 0; nt < 8; nt++) {
                asm("cvt.rna.tf32.f32 %0, %1;" : "=r"(b0[nt]) : "f"(v0[nt]));
                asm("cvt.rna.tf32.f32 %0, %1;" : "=r"(b1[nt]) : "f"(v1[nt]));
            }

#define MMA_ONE(ACC, A, B0, B1)                                                \
    asm volatile("mma.sync.aligned.m16n8k8.row.col.f32.tf32.tf32.f32 "         \
                 "{%0,%1,%2,%3},{%4,%5,%6,%7},{%8,%9},{%0,%1,%2,%3};"          \
                 : "+f"(ACC[0]), "+f"(ACC[1]), "+f"(ACC[2]), "+f"(ACC[3])      \
                 : "r"(A.x), "r"(A.y), "r"(A.z), "r"(A.w), "r"(B0), "r"(B1))
#pragma unroll
            for (int nt = 0; nt < 8; nt++) {
                MMA_ONE(acc[0][nt], A0, b0[nt], b1[nt]);
                MMA_ONE(acc[1][nt], A1, b0[nt], b1[nt]);
                MMA_ONE(acc[2][nt], A2, b0[nt], b1[nt]);
                MMA_ONE(acc[3][nt], A3, b0[nt], b1[nt]);
            }
#undef MMA_ONE
            A0 = N0; A1 = N1; A2 = N2; A3 = N3;
        }

        buf++;
        if (buf == NBUF) buf = 0;
    }

    // ---------------- epilogue ----------------
#pragma unroll
    for (int mt = 0; mt < 4; mt++) {
        int co = warpM * 64 + mt * 16 + gid;
#pragma unroll
        for (int nt = 0; nt < 8; nt++) {
            int orow = R + warpN * 2 + (nt >> 2);
            int ow0  = (nt & 3) * 8 + tig * 2;
            float* base = out + (((size_t)b * COUT + co) * OH + orow) * OW + ow0;
            *(float2*)base = make_float2(acc[mt][nt][0], acc[mt][nt][1]);
            *(float2*)(base + 8 * OH * OW) = make_float2(acc[mt][nt][2], acc[mt][nt][3]);
        }
    }
}

extern "C" void kernel_launch(void* const* d_in, const int* in_sizes, int n_in,
                              void* d_out, int out_size) {
    const float* x = (const float*)d_in[0];   // [32,256,64,64]
    const float* w = (const float*)d_in[1];   // [256,256,3,3]
    float* out = (float*)d_out;               // [32,256,32,32]
    (void)in_sizes; (void)n_in; (void)out_size;

    cudaFuncSetAttribute(conv_mma, cudaFuncAttributeMaxDynamicSharedMemorySize, SM_BYTES);

    prep_w<<<(NWA + 255) / 256, 256>>>(w);

    dim3 grid(8, BN);  // 8 row-tiles x 32 batch = 256 CTAs, 256 thr each
    conv_mma<<<grid, 256, SM_BYTES>>>(x, out);
}